// round 1
// baseline (speedup 1.0000x reference)
#include <cuda_runtime.h>
#include <math.h>

#define KNOTS_N 30
#define NSEG (KNOTS_N - 1)
#define EPSV 1e-12

// Scratch state computed once per launch by the prep kernel (allocation-free:
// __device__ globals per harness rules).
struct SplineParams {
    float k0, kmax, dx, inv_dx;
    int uniform;
};
__device__ SplineParams g_p;
__device__ float4 g_e[NSEG];       // per-segment cubic coeffs in s = x - x_k
__device__ float  g_kn[KNOTS_N];   // knots copy for the non-uniform fallback

// ---------------------------------------------------------------------------
// Prep: single thread. Reproduces _pchip_slopes semantics (EPS placement,
// endpoint one-sided slope + limiter), then converts each segment's Hermite
// form into a plain cubic in s = (x - x_k). Done in double so the only error
// vs the fp32 reference is mutual rounding of the same exact cubic (~1e-6).
// ---------------------------------------------------------------------------
__global__ void spline_prep_kernel(const float* __restrict__ knots,
                                   const float* __restrict__ coeffs) {
    double x[KNOTS_N], y[KNOTS_N], h[NSEG], delta[NSEG], d[KNOTS_N];
    for (int i = 0; i < KNOTS_N; i++) {
        x[i] = (double)knots[i];
        y[i] = (double)coeffs[i];
        g_kn[i] = knots[i];
    }
    for (int i = 0; i < NSEG; i++) {
        h[i] = x[i + 1] - x[i];
        delta[i] = (y[i + 1] - y[i]) / (h[i] + EPSV);
    }
    // interior slopes
    for (int i = 1; i < KNOTS_N - 1; i++) {
        double hkm1 = h[i - 1], hk = h[i];
        double w1 = 2.0 * hk + hkm1;
        double w2 = hk + 2.0 * hkm1;
        bool same_sign = (delta[i - 1] * delta[i]) > 0.0;
        double dint = (w1 + w2) / (w1 / (delta[i - 1] + EPSV) + w2 / (delta[i] + EPSV));
        d[i] = same_sign ? dint : 0.0;
    }
    // endpoints with limiter (sequential where-s == else-if here)
    double d0 = ((2.0 * h[0] + h[1]) * delta[0] - h[0] * delta[1]) / (h[0] + h[1] + EPSV);
    if (d0 * delta[0] <= 0.0) d0 = 0.0;
    else if (fabs(d0) > 3.0 * fabs(delta[0])) d0 = 3.0 * delta[0];

    double dN = ((2.0 * h[NSEG - 1] + h[NSEG - 2]) * delta[NSEG - 1]
                 - h[NSEG - 1] * delta[NSEG - 2]) / (h[NSEG - 1] + h[NSEG - 2] + EPSV);
    if (dN * delta[NSEG - 1] <= 0.0) dN = 0.0;
    else if (fabs(dN) > 3.0 * fabs(delta[NSEG - 1])) dN = 3.0 * delta[NSEG - 1];

    d[0] = d0;
    d[KNOTS_N - 1] = dN;

    // Segment cubic: Hermite(t), t = s/h  ->  e0 + e1*s + e2*s^2 + e3*s^3
    for (int i = 0; i < NSEG; i++) {
        double hh = h[i];
        double yk = y[i], yk1 = y[i + 1], dk = d[i], dk1 = d[i + 1];
        float4 e;
        if (fabs(hh) < EPSV) {
            // reference: t forced to 0 -> y = yk
            e = make_float4((float)yk, 0.0f, 0.0f, 0.0f);
        } else {
            double ih = 1.0 / hh;
            double e2 = (-3.0 * yk - 2.0 * hh * dk + 3.0 * yk1 - hh * dk1) * ih * ih;
            double e3 = (2.0 * yk + hh * dk - 2.0 * yk1 + hh * dk1) * ih * ih * ih;
            e = make_float4((float)yk, (float)dk, (float)e2, (float)e3);
        }
        g_e[i] = e;
    }

    // Uniformity check (loose tolerance; dataset knots are linspace(0,1,30)).
    double range = x[KNOTS_N - 1] - x[0];
    double dxu = range / (double)(KNOTS_N - 1);
    int uni = (dxu > 0.0) ? 1 : 0;
    double tol = 1e-5 * fmax(fabs(range), 1.0);
    for (int i = 0; i < KNOTS_N; i++) {
        double ideal = x[0] + (double)i * dxu;
        if (fabs(x[i] - ideal) > tol) uni = 0;
    }
    g_p.k0 = (float)x[0];
    g_p.kmax = (float)x[KNOTS_N - 1];
    g_p.dx = (float)dxu;
    g_p.inv_dx = (float)(1.0 / dxu);
    g_p.uniform = uni;
}

// ---------------------------------------------------------------------------
// Eval: float4-vectorized streaming kernel. One float4 per thread.
// Per element: clamp, arithmetic segment index (uniform knots) or 5-step
// binary search fallback, one LDS.128 of packed coeffs, 3-FMA Horner.
// ---------------------------------------------------------------------------
__global__ void __launch_bounds__(256)
spline_eval_kernel(const float* __restrict__ x, float* __restrict__ out, int n) {
    __shared__ float4 s_e[NSEG];
    __shared__ float  s_kn[KNOTS_N];
    const int t = threadIdx.x;
    if (t < NSEG)    s_e[t]  = g_e[t];
    if (t < KNOTS_N) s_kn[t] = g_kn[t];
    __syncthreads();

    const float k0 = g_p.k0;
    const float kmax = g_p.kmax;
    const float dx = g_p.dx;
    const float inv_dx = g_p.inv_dx;
    const int uni = g_p.uniform;

    const int nvec = n >> 2;
    const int gid = blockIdx.x * blockDim.x + t;

    if (gid < nvec) {
        const float4 v = reinterpret_cast<const float4*>(x)[gid];
        float in4[4] = {v.x, v.y, v.z, v.w};
        float r[4];
#pragma unroll
        for (int j = 0; j < 4; j++) {
            float xc = fminf(fmaxf(in4[j], k0), kmax);
            int idx;
            float s;
            if (uni) {
                float f = (xc - k0) * inv_dx;
                idx = (int)f;
                idx = min(idx, NSEG - 1);
                idx = max(idx, 0);
                s = xc - fmaf((float)idx, dx, k0);
            } else {
                // lower_bound: count of knots < xc, then -1, clipped
                int lo = 0, hi = KNOTS_N;
                while (lo < hi) {
                    int mid = (lo + hi) >> 1;
                    if (s_kn[mid] < xc) lo = mid + 1;
                    else hi = mid;
                }
                idx = lo - 1;
                idx = min(idx, NSEG - 1);
                idx = max(idx, 0);
                s = xc - s_kn[idx];
            }
            const float4 e = s_e[idx];
            r[j] = fmaf(fmaf(fmaf(e.w, s, e.z), s, e.y), s, e.x);
        }
        reinterpret_cast<float4*>(out)[gid] = make_float4(r[0], r[1], r[2], r[3]);
    }

    // Tail (n % 4 != 0) — handled by first few threads of block 0.
    const int rem = n & 3;
    if (blockIdx.x == 0 && t < rem) {
        const int i = (nvec << 2) + t;
        float xc = fminf(fmaxf(x[i], k0), kmax);
        int idx;
        float s;
        if (uni) {
            float f = (xc - k0) * inv_dx;
            idx = (int)f;
            idx = min(idx, NSEG - 1);
            idx = max(idx, 0);
            s = xc - fmaf((float)idx, dx, k0);
        } else {
            int lo = 0, hi = KNOTS_N;
            while (lo < hi) {
                int mid = (lo + hi) >> 1;
                if (s_kn[mid] < xc) lo = mid + 1;
                else hi = mid;
            }
            idx = lo - 1;
            idx = min(idx, NSEG - 1);
            idx = max(idx, 0);
            s = xc - s_kn[idx];
        }
        const float4 e = s_e[idx];
        out[i] = fmaf(fmaf(fmaf(e.w, s, e.z), s, e.y), s, e.x);
    }
}

extern "C" void kernel_launch(void* const* d_in, const int* in_sizes, int n_in,
                              void* d_out, int out_size) {
    const float* x      = (const float*)d_in[0];
    const float* knots  = (const float*)d_in[1];
    const float* coeffs = (const float*)d_in[2];
    float* out = (float*)d_out;
    const int n = in_sizes[0];

    spline_prep_kernel<<<1, 1>>>(knots, coeffs);

    const int nvec = n >> 2;
    int grid = (nvec + 255) / 256;
    if (grid < 1) grid = 1;
    spline_eval_kernel<<<grid, 256>>>(x, out, n);
}

// round 2
// speedup vs baseline: 2.8583x; 2.8583x over previous
#include <cuda_runtime.h>
#include <math.h>

#define KNOTS_N 30
#define NSEG (KNOTS_N - 1)
#define EPSV 1e-12

// Per-launch spline state (allocation-free __device__ globals).
struct SplineParams {
    float inv_dx;   // 1/dx for uniform knots
    float nb;       // -k0 * inv_dx  (so f = fma(x, inv_dx, nb))
    int uniform;
};
__device__ SplineParams g_p;
// t-domain cubic coefficients, SoA: y(t) = c0 + c1*t + c2*t^2 + c3*t^3
__device__ float g_c0[NSEG], g_c1[NSEG], g_c2[NSEG], g_c3[NSEG];
__device__ float g_kn[KNOTS_N];    // knots (non-uniform fallback)
__device__ float g_ih[NSEG];       // 1/h per segment (non-uniform fallback)

// ---------------------------------------------------------------------------
// Prep: ONE warp, parallel over knots/segments. Reproduces _pchip_slopes
// semantics (EPS placement, endpoint one-sided slope + limiter) in double,
// then emits t-domain coefficients (no division by h needed in eval):
//   c0 = yk, c1 = h*dk, c2 = -3yk - 2h*dk + 3yk1 - h*dk1,
//   c3 = 2yk + h*dk - 2yk1 + h*dk1
// ---------------------------------------------------------------------------
__global__ void spline_prep_kernel(const float* __restrict__ knots,
                                   const float* __restrict__ coeffs) {
    __shared__ double xs[KNOTS_N], ys[KNOTS_N], h[NSEG], delta[NSEG], d[KNOTS_N];
    const int t = threadIdx.x;

    if (t < KNOTS_N) {
        xs[t] = (double)knots[t];
        ys[t] = (double)coeffs[t];
        g_kn[t] = knots[t];
    }
    __syncthreads();

    if (t < NSEG) {
        double hh = xs[t + 1] - xs[t];
        h[t] = hh;
        delta[t] = (ys[t + 1] - ys[t]) / (hh + EPSV);
    }
    __syncthreads();

    // Slopes
    if (t >= 1 && t < KNOTS_N - 1) {
        double hkm1 = h[t - 1], hk = h[t];
        double w1 = 2.0 * hk + hkm1;
        double w2 = hk + 2.0 * hkm1;
        bool same_sign = (delta[t - 1] * delta[t]) > 0.0;
        double dint = (w1 + w2) / (w1 / (delta[t - 1] + EPSV) + w2 / (delta[t] + EPSV));
        d[t] = same_sign ? dint : 0.0;
    }
    if (t == 0) {
        double d0 = ((2.0 * h[0] + h[1]) * delta[0] - h[0] * delta[1])
                    / (h[0] + h[1] + EPSV);
        if (d0 * delta[0] <= 0.0) d0 = 0.0;
        else if (fabs(d0) > 3.0 * fabs(delta[0])) d0 = 3.0 * delta[0];
        d[0] = d0;
    }
    if (t == KNOTS_N - 1) {
        double dN = ((2.0 * h[NSEG - 1] + h[NSEG - 2]) * delta[NSEG - 1]
                     - h[NSEG - 1] * delta[NSEG - 2])
                    / (h[NSEG - 1] + h[NSEG - 2] + EPSV);
        if (dN * delta[NSEG - 1] <= 0.0) dN = 0.0;
        else if (fabs(dN) > 3.0 * fabs(delta[NSEG - 1])) dN = 3.0 * delta[NSEG - 1];
        d[KNOTS_N - 1] = dN;
    }
    __syncthreads();

    // t-domain coefficients per segment
    if (t < NSEG) {
        double hh = h[t];
        double yk = ys[t], yk1 = ys[t + 1], dk = d[t], dk1 = d[t + 1];
        if (fabs(hh) < EPSV) {
            // reference forces t=0 on degenerate segments -> y = yk
            g_c0[t] = (float)yk; g_c1[t] = 0.0f; g_c2[t] = 0.0f; g_c3[t] = 0.0f;
            g_ih[t] = 0.0f;
        } else {
            double hdk = hh * dk, hdk1 = hh * dk1;
            g_c0[t] = (float)yk;
            g_c1[t] = (float)hdk;
            g_c2[t] = (float)(-3.0 * yk - 2.0 * hdk + 3.0 * yk1 - hdk1);
            g_c3[t] = (float)(2.0 * yk + hdk - 2.0 * yk1 + hdk1);
            g_ih[t] = (float)(1.0 / hh);
        }
    }

    // Uniformity check + params (thread 0)
    if (t == 0) {
        double range = xs[KNOTS_N - 1] - xs[0];
        double dxu = range / (double)(KNOTS_N - 1);
        int uni = (dxu > 0.0) ? 1 : 0;
        double tol = 1e-5 * fmax(fabs(range), 1.0);
        for (int i = 0; i < KNOTS_N; i++) {
            double ideal = xs[0] + (double)i * dxu;
            if (fabs(xs[i] - ideal) > tol) uni = 0;
        }
        double inv_dx = (dxu > 0.0) ? (1.0 / dxu) : 0.0;
        g_p.inv_dx = (float)inv_dx;
        g_p.nb = (float)(-xs[0] * inv_dx);
        g_p.uniform = uni;
    }
}

// ---------------------------------------------------------------------------
// Eval: 2 float4 per thread, SoA shared coefficient tables (29 words per
// array -> 29 distinct banks -> conflict-free for arbitrary divergent idx).
// Uniform-knot fast path: f = fma(x,inv_dx,nb); clamp; t = f - floor(f).
// ---------------------------------------------------------------------------
#define TPB 256
#define VEC_PER_THREAD 2

__device__ __forceinline__ float eval_one(float xv,
                                          const float* s_c0, const float* s_c1,
                                          const float* s_c2, const float* s_c3,
                                          float inv_dx, float nb) {
    float f = fmaf(xv, inv_dx, nb);
    f = fminf(fmaxf(f, 0.0f), (float)NSEG);
    float fi = fminf(floorf(f), (float)(NSEG - 1));
    int idx = (int)fi;
    float tt = f - fi;
    float c3 = s_c3[idx], c2 = s_c2[idx], c1 = s_c1[idx], c0 = s_c0[idx];
    return fmaf(fmaf(fmaf(c3, tt, c2), tt, c1), tt, c0);
}

__device__ __forceinline__ float eval_one_nu(float xv,
                                             const float* s_c0, const float* s_c1,
                                             const float* s_c2, const float* s_c3,
                                             const float* s_kn, const float* s_ih,
                                             float klo, float khi) {
    float xc = fminf(fmaxf(xv, klo), khi);
    int lo = 0, hi = KNOTS_N;
    while (lo < hi) {
        int mid = (lo + hi) >> 1;
        if (s_kn[mid] < xc) lo = mid + 1;
        else hi = mid;
    }
    int idx = max(min(lo - 1, NSEG - 1), 0);
    float tt = (xc - s_kn[idx]) * s_ih[idx];
    float c3 = s_c3[idx], c2 = s_c2[idx], c1 = s_c1[idx], c0 = s_c0[idx];
    return fmaf(fmaf(fmaf(c3, tt, c2), tt, c1), tt, c0);
}

__global__ void __launch_bounds__(TPB)
spline_eval_kernel(const float* __restrict__ x, float* __restrict__ out, int n) {
    __shared__ float s_c0[NSEG], s_c1[NSEG], s_c2[NSEG], s_c3[NSEG];
    __shared__ float s_kn[KNOTS_N], s_ih[NSEG];
    const int t = threadIdx.x;
    if (t < NSEG) {
        s_c0[t] = g_c0[t]; s_c1[t] = g_c1[t];
        s_c2[t] = g_c2[t]; s_c3[t] = g_c3[t];
        s_ih[t] = g_ih[t];
    }
    if (t < KNOTS_N) s_kn[t] = g_kn[t];
    __syncthreads();

    const float inv_dx = g_p.inv_dx;
    const float nb = g_p.nb;
    const int uni = g_p.uniform;
    const float klo = s_kn[0];
    const float khi = s_kn[KNOTS_N - 1];

    const int nvec = n >> 2;
    const int base = blockIdx.x * (TPB * VEC_PER_THREAD) + t;

    if (uni) {
#pragma unroll
        for (int v = 0; v < VEC_PER_THREAD; v++) {
            const int gid = base + v * TPB;
            if (gid < nvec) {
                const float4 in = __ldcs(reinterpret_cast<const float4*>(x) + gid);
                float4 r;
                r.x = eval_one(in.x, s_c0, s_c1, s_c2, s_c3, inv_dx, nb);
                r.y = eval_one(in.y, s_c0, s_c1, s_c2, s_c3, inv_dx, nb);
                r.z = eval_one(in.z, s_c0, s_c1, s_c2, s_c3, inv_dx, nb);
                r.w = eval_one(in.w, s_c0, s_c1, s_c2, s_c3, inv_dx, nb);
                __stcs(reinterpret_cast<float4*>(out) + gid, r);
            }
        }
    } else {
#pragma unroll
        for (int v = 0; v < VEC_PER_THREAD; v++) {
            const int gid = base + v * TPB;
            if (gid < nvec) {
                const float4 in = __ldcs(reinterpret_cast<const float4*>(x) + gid);
                float4 r;
                r.x = eval_one_nu(in.x, s_c0, s_c1, s_c2, s_c3, s_kn, s_ih, klo, khi);
                r.y = eval_one_nu(in.y, s_c0, s_c1, s_c2, s_c3, s_kn, s_ih, klo, khi);
                r.z = eval_one_nu(in.z, s_c0, s_c1, s_c2, s_c3, s_kn, s_ih, klo, khi);
                r.w = eval_one_nu(in.w, s_c0, s_c1, s_c2, s_c3, s_kn, s_ih, klo, khi);
                __stcs(reinterpret_cast<float4*>(out) + gid, r);
            }
        }
    }

    // Tail (n % 4 != 0): first threads of block 0.
    const int rem = n & 3;
    if (blockIdx.x == 0 && t < rem) {
        const int i = (nvec << 2) + t;
        float xv = x[i];
        float r = uni ? eval_one(xv, s_c0, s_c1, s_c2, s_c3, inv_dx, nb)
                      : eval_one_nu(xv, s_c0, s_c1, s_c2, s_c3, s_kn, s_ih, klo, khi);
        out[i] = r;
    }
}

extern "C" void kernel_launch(void* const* d_in, const int* in_sizes, int n_in,
                              void* d_out, int out_size) {
    const float* x      = (const float*)d_in[0];
    const float* knots  = (const float*)d_in[1];
    const float* coeffs = (const float*)d_in[2];
    float* out = (float*)d_out;
    const int n = in_sizes[0];

    spline_prep_kernel<<<1, 32>>>(knots, coeffs);

    const int nvec = n >> 2;
    const int per_block = TPB * VEC_PER_THREAD;
    int grid = (nvec + per_block - 1) / per_block;
    if (grid < 1) grid = 1;
    spline_eval_kernel<<<grid, TPB>>>(x, out, n);
}

// round 3
// speedup vs baseline: 3.4475x; 1.2061x over previous
#include <cuda_runtime.h>
#include <math.h>

#define KNOTS_N 30
#define NSEG (KNOTS_N - 1)
#define EPSF 1e-12f
#define TPB 256
#define VEC 4

// ---------------------------------------------------------------------------
// Single fused kernel. Warp 0 of every block recomputes PCHIP prep (fp32,
// warp-shuffle parallel) in the prologue; other warps wait at the same
// __syncthreads() they already needed for the shared tables. No separate
// prep kernel, no inter-kernel dependency.
//
// t-domain cubic per segment: y(t) = c0 + c1*t + c2*t^2 + c3*t^3,
//   c0=yk, c1=h*dk, c2=-3yk-2h*dk+3yk1-h*dk1, c3=2yk+h*dk-2yk1+h*dk1.
// SoA shared tables (29 words each -> 29 distinct banks -> conflict-free
// for arbitrary divergent idx; duplicates broadcast).
// ---------------------------------------------------------------------------

__device__ __forceinline__ float eval_uni(float xv, const float* s_c0,
                                          const float* s_c1, const float* s_c2,
                                          const float* s_c3, float inv_dx, float nb) {
    float f = fmaf(xv, inv_dx, nb);
    f = fminf(fmaxf(f, 0.0f), (float)NSEG);
    int idx = min((int)f, NSEG - 1);        // trunc == floor (f >= 0)
    float tt = f - (float)idx;
    float c3 = s_c3[idx], c2 = s_c2[idx], c1 = s_c1[idx], c0 = s_c0[idx];
    return fmaf(fmaf(fmaf(c3, tt, c2), tt, c1), tt, c0);
}

__device__ __forceinline__ float eval_nu(float xv, const float* s_c0,
                                         const float* s_c1, const float* s_c2,
                                         const float* s_c3, const float* s_kn,
                                         const float* s_ih, float klo, float khi) {
    float xc = fminf(fmaxf(xv, klo), khi);
    int lo = 0, hi = KNOTS_N;
    while (lo < hi) {
        int mid = (lo + hi) >> 1;
        if (s_kn[mid] < xc) lo = mid + 1;
        else hi = mid;
    }
    int idx = max(min(lo - 1, NSEG - 1), 0);
    float tt = (xc - s_kn[idx]) * s_ih[idx];
    float c3 = s_c3[idx], c2 = s_c2[idx], c1 = s_c1[idx], c0 = s_c0[idx];
    return fmaf(fmaf(fmaf(c3, tt, c2), tt, c1), tt, c0);
}

__global__ void __launch_bounds__(TPB)
spline_fused_kernel(const float* __restrict__ x,
                    const float* __restrict__ knots,
                    const float* __restrict__ coeffs,
                    float* __restrict__ out, int n) {
    __shared__ float s_c0[NSEG], s_c1[NSEG], s_c2[NSEG], s_c3[NSEG];
    __shared__ float s_kn[KNOTS_N], s_ih[NSEG];
    __shared__ float s_invdx, s_nb;
    __shared__ int s_uni;

    const int t = threadIdx.x;

    // ---- Prep (warp 0 only, fp32, shuffle-parallel) ----
    if (t < 32) {
        const unsigned FULL = 0xFFFFFFFFu;
        const bool kv = (t < KNOTS_N);   // lanes 0..29 hold a knot
        const bool sv = (t < NSEG);      // lanes 0..28 hold a segment

        float xt = kv ? knots[t]  : 0.0f;
        float yt = kv ? coeffs[t] : 0.0f;

        // h_t = x_{t+1} - x_t ; delta_t = (y_{t+1}-y_t)/(h_t+EPS)   (t < 29)
        float xn = __shfl_down_sync(FULL, xt, 1);
        float yn = __shfl_down_sync(FULL, yt, 1);
        float h = xn - xt;
        float delta = (yn - yt) / (h + EPSF);

        float h_m1 = __shfl_up_sync(FULL, h, 1);
        float d_m1 = __shfl_up_sync(FULL, delta, 1);

        // interior slopes (t = 1..28)
        float d = 0.0f;
        if (t >= 1 && t < KNOTS_N - 1) {
            float w1 = 2.0f * h + h_m1;
            float w2 = h + 2.0f * h_m1;
            bool same = (d_m1 * delta) > 0.0f;
            float dint = (w1 + w2) / (w1 / (d_m1 + EPSF) + w2 / (delta + EPSF));
            d = same ? dint : 0.0f;
        }
        // endpoint slopes (broadcast needed h/delta values)
        float h0  = __shfl_sync(FULL, h, 0),      h1  = __shfl_sync(FULL, h, 1);
        float de0 = __shfl_sync(FULL, delta, 0),  de1 = __shfl_sync(FULL, delta, 1);
        float hN1 = __shfl_sync(FULL, h, NSEG-1), hN2 = __shfl_sync(FULL, h, NSEG-2);
        float dN1 = __shfl_sync(FULL, delta, NSEG-1), dN2 = __shfl_sync(FULL, delta, NSEG-2);
        if (t == 0) {
            float d0 = ((2.0f * h0 + h1) * de0 - h0 * de1) / (h0 + h1 + EPSF);
            if (d0 * de0 <= 0.0f) d0 = 0.0f;
            else if (fabsf(d0) > 3.0f * fabsf(de0)) d0 = 3.0f * de0;
            d = d0;
        }
        if (t == KNOTS_N - 1) {
            float dN = ((2.0f * hN1 + hN2) * dN1 - hN1 * dN2) / (hN1 + hN2 + EPSF);
            if (dN * dN1 <= 0.0f) dN = 0.0f;
            else if (fabsf(dN) > 3.0f * fabsf(dN1)) dN = 3.0f * dN1;
            d = dN;
        }

        // segment coefficients (t < 29); needs d_{t+1}, y_{t+1}
        float d_p1 = __shfl_down_sync(FULL, d, 1);
        if (sv) {
            if (fabsf(h) < EPSF) {
                // reference forces t=0 on degenerate segments -> y = yk
                s_c0[t] = yt; s_c1[t] = 0.0f; s_c2[t] = 0.0f; s_c3[t] = 0.0f;
                s_ih[t] = 0.0f;
            } else {
                float hdk = h * d, hdk1 = h * d_p1;
                s_c0[t] = yt;
                s_c1[t] = hdk;
                s_c2[t] = fmaf(-2.0f, hdk, fmaf(3.0f, yn - yt, -hdk1));
                s_c3[t] = fmaf(2.0f, yt - yn, hdk + hdk1);
                s_ih[t] = 1.0f / h;
            }
        }
        if (kv) s_kn[t] = xt;

        // uniformity check + params
        float k0   = __shfl_sync(FULL, xt, 0);
        float kend = __shfl_sync(FULL, xt, KNOTS_N - 1);
        float range = kend - k0;
        float dxu = range / (float)NSEG;
        float tol = 1e-5f * fmaxf(fabsf(range), 1.0f);
        bool ok = !kv || (fabsf(xt - fmaf((float)t, dxu, k0)) <= tol);
        bool uni = __all_sync(FULL, ok) && (dxu > 0.0f);
        if (t == 0) {
            float inv_dx = (dxu > 0.0f) ? (1.0f / dxu) : 0.0f;
            s_invdx = inv_dx;
            s_nb = -k0 * inv_dx;
            s_uni = uni ? 1 : 0;
        }
    }
    __syncthreads();

    const float inv_dx = s_invdx;
    const float nb = s_nb;
    const int uni = s_uni;
    const float klo = s_kn[0];
    const float khi = s_kn[KNOTS_N - 1];

    const int nvec = n >> 2;
    const int base = blockIdx.x * (TPB * VEC) + t;

    // Front-batched loads for MLP, then compute+store.
    float4 v[VEC];
    bool ok[VEC];
#pragma unroll
    for (int i = 0; i < VEC; i++) {
        const int gid = base + i * TPB;
        ok[i] = (gid < nvec);
        if (ok[i]) v[i] = __ldcs(reinterpret_cast<const float4*>(x) + gid);
    }

    if (uni) {
#pragma unroll
        for (int i = 0; i < VEC; i++) {
            if (ok[i]) {
                float4 r;
                r.x = eval_uni(v[i].x, s_c0, s_c1, s_c2, s_c3, inv_dx, nb);
                r.y = eval_uni(v[i].y, s_c0, s_c1, s_c2, s_c3, inv_dx, nb);
                r.z = eval_uni(v[i].z, s_c0, s_c1, s_c2, s_c3, inv_dx, nb);
                r.w = eval_uni(v[i].w, s_c0, s_c1, s_c2, s_c3, inv_dx, nb);
                __stcs(reinterpret_cast<float4*>(out) + (base + i * TPB), r);
            }
        }
    } else {
#pragma unroll
        for (int i = 0; i < VEC; i++) {
            if (ok[i]) {
                float4 r;
                r.x = eval_nu(v[i].x, s_c0, s_c1, s_c2, s_c3, s_kn, s_ih, klo, khi);
                r.y = eval_nu(v[i].y, s_c0, s_c1, s_c2, s_c3, s_kn, s_ih, klo, khi);
                r.z = eval_nu(v[i].z, s_c0, s_c1, s_c2, s_c3, s_kn, s_ih, klo, khi);
                r.w = eval_nu(v[i].w, s_c0, s_c1, s_c2, s_c3, s_kn, s_ih, klo, khi);
                __stcs(reinterpret_cast<float4*>(out) + (base + i * TPB), r);
            }
        }
    }

    // Tail (n % 4 != 0): first threads of block 0.
    const int rem = n & 3;
    if (blockIdx.x == 0 && t < rem) {
        const int i = (nvec << 2) + t;
        float xv = x[i];
        out[i] = uni ? eval_uni(xv, s_c0, s_c1, s_c2, s_c3, inv_dx, nb)
                     : eval_nu(xv, s_c0, s_c1, s_c2, s_c3, s_kn, s_ih, klo, khi);
    }
}

extern "C" void kernel_launch(void* const* d_in, const int* in_sizes, int n_in,
                              void* d_out, int out_size) {
    const float* x      = (const float*)d_in[0];
    const float* knots  = (const float*)d_in[1];
    const float* coeffs = (const float*)d_in[2];
    float* out = (float*)d_out;
    const int n = in_sizes[0];

    const int nvec = n >> 2;
    const int per_block = TPB * VEC;
    int grid = (nvec + per_block - 1) / per_block;
    if (grid < 1) grid = 1;
    spline_fused_kernel<<<grid, TPB>>>(x, knots, coeffs, out, n);
}

// round 4
// speedup vs baseline: 3.6259x; 1.0517x over previous
#include <cuda_runtime.h>
#include <math.h>

#define KNOTS_N 30
#define NSEG (KNOTS_N - 1)
#define EPSF 1e-12f
#define TPB 256
#define VEC 4

// ---------------------------------------------------------------------------
// Fused kernel: warp 0 of each block recomputes PCHIP prep (fp32, shuffle-
// parallel) in the prologue; all warps then stream x -> spline(x).
// t-domain cubic per segment, SoA shared tables (29 words -> 29 banks ->
// conflict-free divergent lookups).
// Template EXACT: no bounds checks / no tail when nvec % (TPB*VEC) == 0.
// ---------------------------------------------------------------------------

struct Tables {
    float c0[NSEG], c1[NSEG], c2[NSEG], c3[NSEG];
    float kn[KNOTS_N], ih[NSEG];
    float invdx, nb;
    int uni;
};

__device__ __forceinline__ void prep_warp0(const float* __restrict__ knots,
                                           const float* __restrict__ coeffs,
                                           Tables* s) {
    const int t = threadIdx.x;
    const unsigned FULL = 0xFFFFFFFFu;
    const bool kv = (t < KNOTS_N);
    const bool sv = (t < NSEG);

    float xt = kv ? knots[t]  : 0.0f;
    float yt = kv ? coeffs[t] : 0.0f;

    float xn = __shfl_down_sync(FULL, xt, 1);
    float yn = __shfl_down_sync(FULL, yt, 1);
    float h = xn - xt;
    float delta = (yn - yt) / (h + EPSF);

    float h_m1 = __shfl_up_sync(FULL, h, 1);
    float d_m1 = __shfl_up_sync(FULL, delta, 1);

    float d = 0.0f;
    if (t >= 1 && t < KNOTS_N - 1) {
        float w1 = 2.0f * h + h_m1;
        float w2 = h + 2.0f * h_m1;
        bool same = (d_m1 * delta) > 0.0f;
        float dint = (w1 + w2) / (w1 / (d_m1 + EPSF) + w2 / (delta + EPSF));
        d = same ? dint : 0.0f;
    }
    {
        float h0  = __shfl_sync(FULL, h, 0),      h1  = __shfl_sync(FULL, h, 1);
        float de0 = __shfl_sync(FULL, delta, 0),  de1 = __shfl_sync(FULL, delta, 1);
        if (t == 0) {
            float d0 = ((2.0f * h0 + h1) * de0 - h0 * de1) / (h0 + h1 + EPSF);
            if (d0 * de0 <= 0.0f) d0 = 0.0f;
            else if (fabsf(d0) > 3.0f * fabsf(de0)) d0 = 3.0f * de0;
            d = d0;
        }
    }
    {
        float hN1 = __shfl_sync(FULL, h, NSEG-1), hN2 = __shfl_sync(FULL, h, NSEG-2);
        float dN1 = __shfl_sync(FULL, delta, NSEG-1), dN2 = __shfl_sync(FULL, delta, NSEG-2);
        if (t == KNOTS_N - 1) {
            float dN = ((2.0f * hN1 + hN2) * dN1 - hN1 * dN2) / (hN1 + hN2 + EPSF);
            if (dN * dN1 <= 0.0f) dN = 0.0f;
            else if (fabsf(dN) > 3.0f * fabsf(dN1)) dN = 3.0f * dN1;
            d = dN;
        }
    }

    float d_p1 = __shfl_down_sync(FULL, d, 1);
    if (sv) {
        if (fabsf(h) < EPSF) {
            s->c0[t] = yt; s->c1[t] = 0.0f; s->c2[t] = 0.0f; s->c3[t] = 0.0f;
            s->ih[t] = 0.0f;
        } else {
            float hdk = h * d, hdk1 = h * d_p1;
            s->c0[t] = yt;
            s->c1[t] = hdk;
            s->c2[t] = fmaf(-2.0f, hdk, fmaf(3.0f, yn - yt, -hdk1));
            s->c3[t] = fmaf(2.0f, yt - yn, hdk + hdk1);
            s->ih[t] = 1.0f / h;
        }
    }
    if (kv) s->kn[t] = xt;

    float k0   = __shfl_sync(FULL, xt, 0);
    float kend = __shfl_sync(FULL, xt, KNOTS_N - 1);
    float range = kend - k0;
    float dxu = range / (float)NSEG;
    float tol = 1e-5f * fmaxf(fabsf(range), 1.0f);
    bool okk = !kv || (fabsf(xt - fmaf((float)t, dxu, k0)) <= tol);
    bool uni = __all_sync(FULL, okk) && (dxu > 0.0f);
    if (t == 0) {
        float inv_dx = (dxu > 0.0f) ? (1.0f / dxu) : 0.0f;
        s->invdx = inv_dx;
        s->nb = -k0 * inv_dx;
        s->uni = uni ? 1 : 0;
    }
}

__device__ __forceinline__ float eval_uni(float xv, const Tables* s,
                                          float inv_dx, float nb) {
    float f = fmaf(xv, inv_dx, nb);
    f = fminf(fmaxf(f, 0.0f), (float)NSEG);
    int idx = min((int)f, NSEG - 1);
    float tt = f - (float)idx;
    return fmaf(fmaf(fmaf(s->c3[idx], tt, s->c2[idx]), tt, s->c1[idx]), tt, s->c0[idx]);
}

__device__ __forceinline__ float eval_nu(float xv, const Tables* s,
                                         float klo, float khi) {
    float xc = fminf(fmaxf(xv, klo), khi);
    int lo = 0, hi = KNOTS_N;
    while (lo < hi) {
        int mid = (lo + hi) >> 1;
        if (s->kn[mid] < xc) lo = mid + 1;
        else hi = mid;
    }
    int idx = max(min(lo - 1, NSEG - 1), 0);
    float tt = (xc - s->kn[idx]) * s->ih[idx];
    return fmaf(fmaf(fmaf(s->c3[idx], tt, s->c2[idx]), tt, s->c1[idx]), tt, s->c0[idx]);
}

template <bool EXACT>
__global__ void __launch_bounds__(TPB, 8)
spline_fused_kernel(const float* __restrict__ x,
                    const float* __restrict__ knots,
                    const float* __restrict__ coeffs,
                    float* __restrict__ out, int n) {
    __shared__ Tables s;
    const int t = threadIdx.x;

    if (t < 32) prep_warp0(knots, coeffs, &s);
    __syncthreads();

    const float inv_dx = s.invdx;
    const float nb = s.nb;
    const int uni = s.uni;

    const int nvec = n >> 2;
    const int base = blockIdx.x * (TPB * VEC) + t;
    const float4* __restrict__ xv = reinterpret_cast<const float4*>(x);
    float4* __restrict__ ov = reinterpret_cast<float4*>(out);

    if (uni) {
        // 2+2 staged pipeline: keeps MLP while fitting the 32-reg budget.
        float4 a, b;
        if (EXACT || base < nvec)              a = __ldcs(xv + base);
        if (EXACT || base + TPB < nvec)        b = __ldcs(xv + base + TPB);
#pragma unroll
        for (int i = 0; i < VEC; i++) {
            const int gid = base + i * TPB;
            if (EXACT || gid < nvec) {
                float4 v = (i & 1) ? b : a;
                // prefetch two ahead into the slot just consumed
                const int pf = gid + 2 * TPB;
                if (i + 2 < VEC && (EXACT || pf < nvec)) {
                    if (i & 1) b = __ldcs(xv + pf);
                    else       a = __ldcs(xv + pf);
                }
                float4 r;
                r.x = eval_uni(v.x, &s, inv_dx, nb);
                r.y = eval_uni(v.y, &s, inv_dx, nb);
                r.z = eval_uni(v.z, &s, inv_dx, nb);
                r.w = eval_uni(v.w, &s, inv_dx, nb);
                __stcs(ov + gid, r);
            }
        }
    } else {
        const float klo = s.kn[0];
        const float khi = s.kn[KNOTS_N - 1];
#pragma unroll
        for (int i = 0; i < VEC; i++) {
            const int gid = base + i * TPB;
            if (EXACT || gid < nvec) {
                float4 v = __ldcs(xv + gid);
                float4 r;
                r.x = eval_nu(v.x, &s, klo, khi);
                r.y = eval_nu(v.y, &s, klo, khi);
                r.z = eval_nu(v.z, &s, klo, khi);
                r.w = eval_nu(v.w, &s, klo, khi);
                __stcs(ov + gid, r);
            }
        }
    }

    if (!EXACT) {
        const int rem = n & 3;
        if (blockIdx.x == 0 && t < rem) {
            const int i = (nvec << 2) + t;
            float xvv = x[i];
            out[i] = uni ? eval_uni(xvv, &s, inv_dx, nb)
                         : eval_nu(xvv, &s, s.kn[0], s.kn[KNOTS_N - 1]);
        }
    }
}

extern "C" void kernel_launch(void* const* d_in, const int* in_sizes, int n_in,
                              void* d_out, int out_size) {
    const float* x      = (const float*)d_in[0];
    const float* knots  = (const float*)d_in[1];
    const float* coeffs = (const float*)d_in[2];
    float* out = (float*)d_out;
    const int n = in_sizes[0];

    const int nvec = n >> 2;
    const int per_block = TPB * VEC;

    if (n >= 4 && (n & 3) == 0 && (nvec % per_block) == 0) {
        const int grid = nvec / per_block;
        spline_fused_kernel<true><<<grid, TPB>>>(x, knots, coeffs, out, n);
    } else {
        int grid = (nvec + per_block - 1) / per_block;
        if (grid < 1) grid = 1;
        spline_fused_kernel<false><<<grid, TPB>>>(x, knots, coeffs, out, n);
    }
}